// round 4
// baseline (speedup 1.0000x reference)
#include <cuda_runtime.h>
#include <cstdint>
#include <math.h>

// Problem constants
constexpr int Bb  = 8;
constexpr int SEQ = 1024;
constexpr int Hh  = 8;
constexpr int DH  = 64;
constexpr int Mrows = Bb * SEQ;   // 8192
constexpr int KD = 512;
constexpr int ND = 512;
constexpr float SCALE = 0.04419417382415922f;   // 1/sqrt(512)

// Scratch (device globals: allocation-free rule)
__device__ float g_x[3][Mrows * ND];   // tf32-rounded inputs
__device__ float g_q[Mrows * ND];      // tf32-rounded, pre-scaled Q proj
__device__ float g_k[Mrows * ND];      // tf32-rounded K proj
__device__ float g_v[Mrows * ND];      // tf32-rounded V proj
__device__ float g_o[Mrows * ND];      // tf32-rounded attention output
__device__ float g_wt[4][KD * ND];     // transposed + tf32-rounded weights

// ---------------------------------------------------------------------------
// Helpers
// ---------------------------------------------------------------------------
__device__ __forceinline__ uint32_t f2tf32(float x) {
    uint32_t r;
    asm("cvt.rna.tf32.f32 %0, %1;" : "=r"(r) : "f"(x));
    return r;
}
__device__ __forceinline__ float rtf(float x) {
    return __uint_as_float(f2tf32(x));
}

__device__ __forceinline__ void mma_tf32(float c[4], const uint32_t a[4],
                                         const uint32_t b[2]) {
    asm volatile(
        "mma.sync.aligned.m16n8k8.row.col.f32.tf32.tf32.f32 "
        "{%0,%1,%2,%3}, {%4,%5,%6,%7}, {%8,%9}, {%0,%1,%2,%3};"
        : "+f"(c[0]), "+f"(c[1]), "+f"(c[2]), "+f"(c[3])
        : "r"(a[0]), "r"(a[1]), "r"(a[2]), "r"(a[3]),
          "r"(b[0]), "r"(b[1]));
}

__device__ __forceinline__ uint32_t smem_u32(const void* p) {
    uint32_t a;
    asm("{ .reg .u64 t; cvta.to.shared.u64 t, %1; cvt.u32.u64 %0, t; }"
        : "=r"(a) : "l"(p));
    return a;
}

__device__ __forceinline__ void cp16(uint32_t dst, const void* src) {
    asm volatile("cp.async.cg.shared.global [%0], [%1], 16;"
                 :: "r"(dst), "l"(src) : "memory");
}
#define CP_COMMIT() asm volatile("cp.async.commit_group;" ::: "memory")
#define CP_WAIT(n)  asm volatile("cp.async.wait_group %0;" :: "n"(n) : "memory")

// ---------------------------------------------------------------------------
// Prep: tf32-round the three input activations into g_x
// ---------------------------------------------------------------------------
__global__ void round_inputs(const float* __restrict__ q,
                             const float* __restrict__ k,
                             const float* __restrict__ v)
{
    const float* src = (blockIdx.y == 0) ? q : (blockIdx.y == 1) ? k : v;
    float* dst = g_x[blockIdx.y];
    const int total = Mrows * ND / 4;
    for (int i = blockIdx.x * blockDim.x + threadIdx.x; i < total;
         i += gridDim.x * blockDim.x) {
        float4 t = ((const float4*)src)[i];
        t.x = rtf(t.x); t.y = rtf(t.y); t.z = rtf(t.z); t.w = rtf(t.w);
        ((float4*)dst)[i] = t;
    }
}

// ---------------------------------------------------------------------------
// Weight transpose + tf32 round: Wt[n][k] = round(W[k][n])
// ---------------------------------------------------------------------------
__global__ void transposeW(const float* __restrict__ Wq,
                           const float* __restrict__ Wk,
                           const float* __restrict__ Wv,
                           const float* __restrict__ Wo)
{
    __shared__ float tile[32][33];
    const float* src;
    switch (blockIdx.z) {
        case 0: src = Wq; break;
        case 1: src = Wk; break;
        case 2: src = Wv; break;
        default: src = Wo; break;
    }
    float* dst = g_wt[blockIdx.z];

    int x = blockIdx.x * 32 + threadIdx.x;
    int y = blockIdx.y * 32 + threadIdx.y;
    #pragma unroll
    for (int j = 0; j < 32; j += 8)
        tile[threadIdx.y + j][threadIdx.x] = rtf(src[(size_t)(y + j) * ND + x]);
    __syncthreads();
    int x2 = blockIdx.y * 32 + threadIdx.x;
    int y2 = blockIdx.x * 32 + threadIdx.y;
    #pragma unroll
    for (int j = 0; j < 32; j += 8)
        dst[(size_t)(y2 + j) * KD + x2] = tile[threadIdx.x][threadIdx.y + j];
}

// ---------------------------------------------------------------------------
// tf32 mma GEMM with 2-stage cp.async pipeline.
// C[128,128] tile = A[M,512] @ Bt[N,512]^T + bias.  A, Bt pre-tf32-rounded.
// 256 threads = 8 warps (4m x 2n); warp tile 32m x 64n; K-chunk 32.
// ---------------------------------------------------------------------------
constexpr int GS = 36;                         // smem row stride (floats)
constexpr int GEMM_STAGE = 128 * GS;           // floats per matrix per stage
constexpr int GEMM_SMEM  = 4 * GEMM_STAGE * 4; // bytes (A0,B0,A1,B1) = 73728

template<bool ROUND>
__device__ __forceinline__ void gemm_cp_body(const float* __restrict__ A,
                                             const float* __restrict__ Bt,
                                             const float* __restrict__ bias,
                                             float scale,
                                             float* __restrict__ C)
{
    extern __shared__ float sm[];
    float* sAp[2] = { sm,                  sm + 2 * GEMM_STAGE };
    float* sBp[2] = { sm + GEMM_STAGE,     sm + 3 * GEMM_STAGE };

    const int t   = threadIdx.x;
    const int wid = t >> 5;
    const int lid = t & 31;
    const int g   = lid >> 2;
    const int tig = lid & 3;
    const int wm  = wid & 3;
    const int wn  = wid >> 2;
    const int m0  = blockIdx.y * 128;
    const int n0  = blockIdx.x * 128;

    float acc[2][8][4] = {};

    auto load_stage = [&](int s, int k0) {
        #pragma unroll
        for (int i = 0; i < 4; i++) {
            int idx = t + i * 256;        // 0..1023
            int r   = idx >> 3;           // 0..127
            int c4  = (idx & 7) << 2;     // 0,4,...,28
            cp16(smem_u32(&sAp[s][r * GS + c4]),
                 A + (size_t)(m0 + r) * KD + k0 + c4);
            cp16(smem_u32(&sBp[s][r * GS + c4]),
                 Bt + (size_t)(n0 + r) * KD + k0 + c4);
        }
        CP_COMMIT();
    };

    load_stage(0, 0);

    for (int it = 0; it < 16; it++) {
        if (it < 15) { load_stage((it + 1) & 1, (it + 1) * 32); CP_WAIT(1); }
        else         { CP_WAIT(0); }
        __syncthreads();

        const float* sA = sAp[it & 1];
        const float* sB = sBp[it & 1];

        #pragma unroll
        for (int ks = 0; ks < 4; ks++) {
            const int kk = ks * 8;
            uint32_t afr[2][4];
            #pragma unroll
            for (int mt = 0; mt < 2; mt++) {
                int row = (wm * 32 + mt * 16 + g) * GS + kk + tig;
                afr[mt][0] = __float_as_uint(sA[row]);
                afr[mt][1] = __float_as_uint(sA[row + 8 * GS]);
                afr[mt][2] = __float_as_uint(sA[row + 4]);
                afr[mt][3] = __float_as_uint(sA[row + 8 * GS + 4]);
            }
            uint32_t bfr[8][2];
            #pragma unroll
            for (int nt = 0; nt < 8; nt++) {
                int rowb = (wn * 64 + nt * 8 + g) * GS + kk + tig;
                bfr[nt][0] = __float_as_uint(sB[rowb]);
                bfr[nt][1] = __float_as_uint(sB[rowb + 4]);
            }
            #pragma unroll
            for (int mt = 0; mt < 2; mt++)
                #pragma unroll
                for (int nt = 0; nt < 8; nt++)
                    mma_tf32(acc[mt][nt], afr[mt], bfr[nt]);
        }
        __syncthreads();
    }

    #pragma unroll
    for (int mt = 0; mt < 2; mt++) {
        int row = m0 + wm * 32 + mt * 16 + g;
        #pragma unroll
        for (int nt = 0; nt < 8; nt++) {
            int col = n0 + wn * 64 + nt * 8 + tig * 2;
            float v00 = (acc[mt][nt][0] + bias[col])     * scale;
            float v01 = (acc[mt][nt][1] + bias[col + 1]) * scale;
            float v10 = (acc[mt][nt][2] + bias[col])     * scale;
            float v11 = (acc[mt][nt][3] + bias[col + 1]) * scale;
            float2 o0, o1;
            if (ROUND) {
                o0 = make_float2(rtf(v00), rtf(v01));
                o1 = make_float2(rtf(v10), rtf(v11));
            } else {
                o0 = make_float2(v00, v01);
                o1 = make_float2(v10, v11);
            }
            *(float2*)(C + (size_t)row * ND + col)       = o0;
            *(float2*)(C + (size_t)(row + 8) * ND + col) = o1;
        }
    }
}

__global__ void __launch_bounds__(256, 2)
qkv_mma(const float* __restrict__ bq, const float* __restrict__ bk,
        const float* __restrict__ bv)
{
    const float* bias;
    float* C;
    float scale;
    if (blockIdx.z == 0)      { bias = bq; C = g_q; scale = SCALE; }
    else if (blockIdx.z == 1) { bias = bk; C = g_k; scale = 1.f; }
    else                      { bias = bv; C = g_v; scale = 1.f; }
    gemm_cp_body<true>(g_x[blockIdx.z], g_wt[blockIdx.z], bias, scale, C);
}

__global__ void __launch_bounds__(256, 2)
out_mma(const float* __restrict__ bo, float* __restrict__ out)
{
    gemm_cp_body<false>(g_o, g_wt[3], bo, 1.f, out);
}

// ---------------------------------------------------------------------------
// Flash attention, tf32 mma, 256 threads, key-tile 64, 2-stage cp.async K/V.
// One block = (b,h) x 64 queries. Warp (wm,wn): q-rows wm*16.., half wn.
// ---------------------------------------------------------------------------
constexpr int AS = 68;                            // row stride (floats)
constexpr int Q_OFF  = 0;                         // 64 x AS
constexpr int K_OFF  = 64 * AS;                   // 2 stages of 64 x AS
constexpr int V_OFF  = K_OFF + 2 * 64 * AS;
constexpr int S_OFF  = V_OFF + 2 * 64 * AS;
constexpr int ATTN_SMEM = (S_OFF + 64 * AS) * 4;  // 104448 bytes

__global__ void __launch_bounds__(256, 2) attn_mma()
{
    extern __shared__ float sm[];
    float* Qs  = sm + Q_OFF;
    float* Ksb = sm + K_OFF;
    float* Vsb = sm + V_OFF;
    float* Ssm = sm + S_OFF;
    __shared__ float mrow[64], lrow[64], frow[64];

    const int t   = threadIdx.x;
    const int wid = t >> 5;
    const int lid = t & 31;
    const int g   = lid >> 2;
    const int tig = lid & 3;
    const int wm  = wid & 3;
    const int wn  = wid >> 2;
    const int q0  = blockIdx.x * 64;
    const int b   = blockIdx.y >> 3;
    const int h   = blockIdx.y & 7;
    const size_t base = (size_t)b * SEQ * ND + (size_t)h * DH;

    const int qrow = wm * 16 + g;

    // Prologue: Q tile (pre-scaled, pre-rounded) + K/V stage 0 via cp.async
    #pragma unroll
    for (int i = 0; i < 4; i++) {
        int idx = t + i * 256;         // 0..1023
        int r   = idx >> 4;            // 0..63
        int c4  = (idx & 15) << 2;
        cp16(smem_u32(&Qs[r * AS + c4]),
             g_q + base + (size_t)(q0 + r) * ND + c4);
    }
    auto load_kv = [&](int s, int k0) {
        float* Ks = Ksb + s * 64 * AS;
        float* Vs = Vsb + s * 64 * AS;
        #pragma unroll
        for (int i = 0; i < 4; i++) {
            int idx = t + i * 256;
            int r   = idx >> 4;
            int c4  = (idx & 15) << 2;
            cp16(smem_u32(&Ks[r * AS + c4]),
                 g_k + base + (size_t)(k0 + r) * ND + c4);
            cp16(smem_u32(&Vs[r * AS + c4]),
                 g_v + base + (size_t)(k0 + r) * ND + c4);
        }
        CP_COMMIT();
    };
    load_kv(0, 0);   // group also covers the Q loads

    if (t < 64) { mrow[t] = -1e30f; lrow[t] = 0.f; }

    float oacc[4][4] = {};   // 16 q-rows x 32 d-cols (this warp's half)

    for (int kt = 0; kt < 16; kt++) {
        if (kt < 15) { load_kv((kt + 1) & 1, (kt + 1) * 64); CP_WAIT(1); }
        else         { CP_WAIT(0); }
        __syncthreads();

        const float* Ks = Ksb + (kt & 1) * 64 * AS;
        const float* Vs = Vsb + (kt & 1) * 64 * AS;

        // S = Qs @ Ks^T : warp covers rows [wm*16,+16) x keys [wn*32,+32)
        float sfr[4][4] = {};
        #pragma unroll
        for (int ks = 0; ks < 8; ks++) {
            const int kk = ks * 8;
            uint32_t afr[4];
            int ra = qrow * AS + kk + tig;
            afr[0] = __float_as_uint(Qs[ra]);
            afr[1] = __float_as_uint(Qs[ra + 8 * AS]);
            afr[2] = __float_as_uint(Qs[ra + 4]);
            afr[3] = __float_as_uint(Qs[ra + 8 * AS + 4]);
            #pragma unroll
            for (int nt = 0; nt < 4; nt++) {
                uint32_t bfr[2];
                int rb = (wn * 32 + nt * 8 + g) * AS + kk + tig;
                bfr[0] = __float_as_uint(Ks[rb]);
                bfr[1] = __float_as_uint(Ks[rb + 4]);
                mma_tf32(sfr[nt], afr, bfr);
            }
        }
        #pragma unroll
        for (int nt = 0; nt < 4; nt++) {
            int col = wn * 32 + nt * 8 + tig * 2;
            *(float2*)&Ssm[qrow * AS + col]       = make_float2(sfr[nt][0], sfr[nt][1]);
            *(float2*)&Ssm[(qrow + 8) * AS + col] = make_float2(sfr[nt][2], sfr[nt][3]);
        }
        __syncthreads();

        // Parallel online softmax: 4 threads per row (16 keys each)
        {
            int row = t >> 2;
            int qtr = t & 3;
            float* p = &Ssm[row * AS + qtr * 16];
            float mx = -1e30f;
            #pragma unroll
            for (int j = 0; j < 16; j++) mx = fmaxf(mx, p[j]);
            mx = fmaxf(mx, __shfl_xor_sync(0xFFFFFFFF, mx, 1));
            mx = fmaxf(mx, __shfl_xor_sync(0xFFFFFFFF, mx, 2));
            float mo = mrow[row];
            float nm = fmaxf(mo, mx);
            float f  = __expf(mo - nm);
            float sum = 0.f;
            #pragma unroll
            for (int j = 0; j < 16; j++) {
                float e = __expf(p[j] - nm);
                sum += e;
                p[j] = rtf(e);
            }
            sum += __shfl_xor_sync(0xFFFFFFFF, sum, 1);
            sum += __shfl_xor_sync(0xFFFFFFFF, sum, 2);
            if (qtr == 0) {
                mrow[row] = nm;
                lrow[row] = lrow[row] * f + sum;
                frow[row] = f;
            }
        }
        __syncthreads();

        // Rescale running O, accumulate P @ V (warp: 16 q x d-cols [wn*32,+32))
        float f0 = frow[qrow];
        float f1 = frow[qrow + 8];
        #pragma unroll
        for (int nt = 0; nt < 4; nt++) {
            oacc[nt][0] *= f0;  oacc[nt][1] *= f0;
            oacc[nt][2] *= f1;  oacc[nt][3] *= f1;
        }
        #pragma unroll
        for (int ks = 0; ks < 8; ks++) {
            const int kk = ks * 8;
            uint32_t afr[4];
            int ra = qrow * AS + kk + tig;
            afr[0] = __float_as_uint(Ssm[ra]);
            afr[1] = __float_as_uint(Ssm[ra + 8 * AS]);
            afr[2] = __float_as_uint(Ssm[ra + 4]);
            afr[3] = __float_as_uint(Ssm[ra + 8 * AS + 4]);
            #pragma unroll
            for (int nt = 0; nt < 4; nt++) {
                uint32_t bfr[2];
                int rb = (kk + tig) * AS + wn * 32 + nt * 8 + g;
                bfr[0] = __float_as_uint(Vs[rb]);
                bfr[1] = __float_as_uint(Vs[rb + 4 * AS]);
                mma_tf32(oacc[nt], afr, bfr);
            }
        }
        __syncthreads();
    }

    // Normalize and write O (tf32-rounded for the cp.async out GEMM)
    float inv0 = 1.f / lrow[qrow];
    float inv1 = 1.f / lrow[qrow + 8];
    #pragma unroll
    for (int nt = 0; nt < 4; nt++) {
        int col = wn * 32 + nt * 8 + tig * 2;
        float2 o0 = make_float2(rtf(oacc[nt][0] * inv0), rtf(oacc[nt][1] * inv0));
        float2 o1 = make_float2(rtf(oacc[nt][2] * inv1), rtf(oacc[nt][3] * inv1));
        *(float2*)(g_o + base + (size_t)(q0 + qrow) * ND + col)     = o0;
        *(float2*)(g_o + base + (size_t)(q0 + qrow + 8) * ND + col) = o1;
    }
}

// ---------------------------------------------------------------------------
extern "C" void kernel_launch(void* const* d_in, const int* in_sizes, int n_in,
                              void* d_out, int out_size)
{
    const float* q  = (const float*)d_in[0];
    const float* k  = (const float*)d_in[1];
    const float* v  = (const float*)d_in[2];
    const float* Wq = (const float*)d_in[3];
    const float* bq = (const float*)d_in[4];
    const float* Wk = (const float*)d_in[5];
    const float* bk = (const float*)d_in[6];
    const float* Wv = (const float*)d_in[7];
    const float* bv = (const float*)d_in[8];
    const float* Wo = (const float*)d_in[9];
    const float* bo = (const float*)d_in[10];

    static bool attr_done = false;
    if (!attr_done) {
        cudaFuncSetAttribute(qkv_mma, cudaFuncAttributeMaxDynamicSharedMemorySize, GEMM_SMEM);
        cudaFuncSetAttribute(out_mma, cudaFuncAttributeMaxDynamicSharedMemorySize, GEMM_SMEM);
        cudaFuncSetAttribute(attn_mma, cudaFuncAttributeMaxDynamicSharedMemorySize, ATTN_SMEM);
        attr_done = true;
    }

    round_inputs<<<dim3(512, 3), 256>>>(q, k, v);
    transposeW<<<dim3(16, 16, 4), dim3(32, 8)>>>(Wq, Wk, Wv, Wo);
    qkv_mma<<<dim3(ND / 128, Mrows / 128, 3), 256, GEMM_SMEM>>>(bq, bk, bv);
    attn_mma<<<dim3(SEQ / 64, Bb * Hh), 256, ATTN_SMEM>>>();
    out_mma<<<dim3(ND / 128, Mrows / 128), 256, GEMM_SMEM>>>(bo, (float*)d_out);
}

// round 5
// speedup vs baseline: 1.1901x; 1.1901x over previous
#include <cuda_runtime.h>
#include <cstdint>
#include <math.h>

// Problem constants
constexpr int Bb  = 8;
constexpr int SEQ = 1024;
constexpr int Hh  = 8;
constexpr int DH  = 64;
constexpr int Mrows = Bb * SEQ;   // 8192
constexpr int KD = 512;
constexpr int ND = 512;
constexpr float SCALE = 0.04419417382415922f;   // 1/sqrt(512)

// Scratch (device globals: allocation-free rule)
__device__ float g_x[3][Mrows * ND];   // tf32-rounded, k-pair-permuted inputs
__device__ float g_q[Mrows * ND];      // rounded, scaled, d-permuted Q proj
__device__ float g_k[Mrows * ND];      // rounded, d-permuted K proj
__device__ float g_v[Mrows * ND];      // rounded V proj (plain layout)
__device__ float g_o[Mrows * ND];      // rounded, d-permuted attention output
__device__ float g_wt[4][KD * ND];     // transposed, rounded, k-permuted weights

// ---------------------------------------------------------------------------
// Helpers
// ---------------------------------------------------------------------------
__device__ __forceinline__ uint32_t f2tf32(float x) {
    uint32_t r;
    asm("cvt.rna.tf32.f32 %0, %1;" : "=r"(r) : "f"(x));
    return r;
}
__device__ __forceinline__ float rtf(float x) {
    return __uint_as_float(f2tf32(x));
}

// Position of k-slot j within its 8-group: layout [0,4,1,5,2,6,3,7]
__device__ __forceinline__ int f8(int j) {
    return ((j & 3) << 1) | ((j >> 2) & 1);
}

__device__ __forceinline__ void mma_tf32(float c[4], const uint32_t a[4],
                                         const uint32_t b[2]) {
    asm volatile(
        "mma.sync.aligned.m16n8k8.row.col.f32.tf32.tf32.f32 "
        "{%0,%1,%2,%3}, {%4,%5,%6,%7}, {%8,%9}, {%0,%1,%2,%3};"
        : "+f"(c[0]), "+f"(c[1]), "+f"(c[2]), "+f"(c[3])
        : "r"(a[0]), "r"(a[1]), "r"(a[2]), "r"(a[3]),
          "r"(b[0]), "r"(b[1]));
}

__device__ __forceinline__ uint32_t smem_u32(const void* p) {
    uint32_t a;
    asm("{ .reg .u64 t; cvta.to.shared.u64 t, %1; cvt.u32.u64 %0, t; }"
        : "=r"(a) : "l"(p));
    return a;
}

__device__ __forceinline__ void cp16(uint32_t dst, const void* src) {
    asm volatile("cp.async.cg.shared.global [%0], [%1], 16;"
                 :: "r"(dst), "l"(src) : "memory");
}
#define CP_COMMIT() asm volatile("cp.async.commit_group;" ::: "memory")
#define CP_WAIT(n)  asm volatile("cp.async.wait_group %0;" :: "n"(n) : "memory")

// ---------------------------------------------------------------------------
// Prep: round + k-pair-permute input activations into g_x
// ---------------------------------------------------------------------------
__global__ void round_inputs(const float* __restrict__ q,
                             const float* __restrict__ k,
                             const float* __restrict__ v)
{
    const float* src = (blockIdx.y == 0) ? q : (blockIdx.y == 1) ? k : v;
    float* dst = g_x[blockIdx.y];
    const int total = Mrows * ND / 8;
    for (int i = blockIdx.x * blockDim.x + threadIdx.x; i < total;
         i += gridDim.x * blockDim.x) {
        const float4 a = ((const float4*)src)[i * 2];
        const float4 b = ((const float4*)src)[i * 2 + 1];
        float4 o0, o1;   // positions [s0,s4,s1,s5] and [s2,s6,s3,s7]
        o0.x = rtf(a.x); o0.y = rtf(b.x); o0.z = rtf(a.y); o0.w = rtf(b.y);
        o1.x = rtf(a.z); o1.y = rtf(b.z); o1.z = rtf(a.w); o1.w = rtf(b.w);
        ((float4*)dst)[i * 2]     = o0;
        ((float4*)dst)[i * 2 + 1] = o1;
    }
}

// ---------------------------------------------------------------------------
// Weight transpose + round + k-permute: Wt[n][perm(k)] = round(W[k][n])
// ---------------------------------------------------------------------------
__global__ void transposeW(const float* __restrict__ Wq,
                           const float* __restrict__ Wk,
                           const float* __restrict__ Wv,
                           const float* __restrict__ Wo)
{
    __shared__ float tile[32][33];
    const float* src;
    switch (blockIdx.z) {
        case 0: src = Wq; break;
        case 1: src = Wk; break;
        case 2: src = Wv; break;
        default: src = Wo; break;
    }
    float* dst = g_wt[blockIdx.z];

    int x = blockIdx.x * 32 + threadIdx.x;
    int y = blockIdx.y * 32 + threadIdx.y;
    #pragma unroll
    for (int j = 0; j < 32; j += 8)
        tile[threadIdx.y + j][threadIdx.x] = rtf(src[(size_t)(y + j) * ND + x]);
    __syncthreads();
    int x2 = blockIdx.y * 32 + threadIdx.x;          // k index
    int x2p = (x2 & ~7) | f8(x2 & 7);                // permuted k position
    int y2 = blockIdx.x * 32 + threadIdx.y;          // n index
    #pragma unroll
    for (int j = 0; j < 32; j += 8)
        dst[(size_t)(y2 + j) * KD + x2p] = tile[threadIdx.x][threadIdx.y + j];
}

// ---------------------------------------------------------------------------
// tf32 mma GEMM, 2-stage cp.async, k-pair layout -> LDS.64 fragments.
// C[128,128] tile = A[M,512] @ Bt[N,512]^T + bias.
// 256 threads = 8 warps (4m x 2n); warp tile 32m x 64n; K-chunk 32.
// Epilogue modes: 0 plain, 1 round, 2 round+perm, 3 round+perm+scale
// ---------------------------------------------------------------------------
constexpr int GS = 40;                         // smem row stride (floats)
constexpr int GEMM_STAGE = 128 * GS;           // floats per matrix per stage
constexpr int GEMM_SMEM  = 4 * GEMM_STAGE * 4; // 81920 bytes

__device__ __forceinline__ void gemm_cp_body(const float* __restrict__ A,
                                             const float* __restrict__ Bt,
                                             const float* __restrict__ bias,
                                             float scale, int mode,
                                             float* __restrict__ C)
{
    extern __shared__ float sm[];
    float* sAp[2] = { sm,              sm + 2 * GEMM_STAGE };
    float* sBp[2] = { sm + GEMM_STAGE, sm + 3 * GEMM_STAGE };

    const int t   = threadIdx.x;
    const int wid = t >> 5;
    const int lid = t & 31;
    const int g   = lid >> 2;
    const int tig = lid & 3;
    const int wm  = wid & 3;
    const int wn  = wid >> 2;
    const int m0  = blockIdx.y * 128;
    const int n0  = blockIdx.x * 128;

    float acc[2][8][4] = {};

    auto load_stage = [&](int s, int k0) {
        #pragma unroll
        for (int i = 0; i < 4; i++) {
            int idx = t + i * 256;        // 0..1023
            int r   = idx >> 3;           // 0..127
            int c4  = (idx & 7) << 2;     // 0,4,...,28
            cp16(smem_u32(&sAp[s][r * GS + c4]),
                 A + (size_t)(m0 + r) * KD + k0 + c4);
            cp16(smem_u32(&sBp[s][r * GS + c4]),
                 Bt + (size_t)(n0 + r) * KD + k0 + c4);
        }
        CP_COMMIT();
    };

    load_stage(0, 0);

    for (int it = 0; it < 16; it++) {
        if (it < 15) { load_stage((it + 1) & 1, (it + 1) * 32); CP_WAIT(1); }
        else         { CP_WAIT(0); }
        __syncthreads();

        const float* sA = sAp[it & 1];
        const float* sB = sBp[it & 1];

        #pragma unroll
        for (int ks = 0; ks < 4; ks++) {
            const int kk = ks * 8;
            uint32_t afr[2][4];
            #pragma unroll
            for (int mt = 0; mt < 2; mt++) {
                int rowa = wm * 32 + mt * 16 + g;
                float2 p0 = *(const float2*)&sA[rowa * GS + kk + 2 * tig];
                float2 p1 = *(const float2*)&sA[(rowa + 8) * GS + kk + 2 * tig];
                afr[mt][0] = __float_as_uint(p0.x);
                afr[mt][1] = __float_as_uint(p1.x);
                afr[mt][2] = __float_as_uint(p0.y);
                afr[mt][3] = __float_as_uint(p1.y);
            }
            uint32_t bfr[8][2];
            #pragma unroll
            for (int nt = 0; nt < 8; nt++) {
                float2 pb = *(const float2*)&sB[(wn * 64 + nt * 8 + g) * GS
                                                + kk + 2 * tig];
                bfr[nt][0] = __float_as_uint(pb.x);
                bfr[nt][1] = __float_as_uint(pb.y);
            }
            #pragma unroll
            for (int mt = 0; mt < 2; mt++)
                #pragma unroll
                for (int nt = 0; nt < 8; nt++)
                    mma_tf32(acc[mt][nt], afr[mt], bfr[nt]);
        }
        __syncthreads();
    }

    // Epilogue
    const int pe = f8(2 * tig);       // permuted position of col 2*tig
    const int po = f8(2 * tig + 1);   // permuted position of col 2*tig+1
    #pragma unroll
    for (int mt = 0; mt < 2; mt++) {
        int row = m0 + wm * 32 + mt * 16 + g;
        #pragma unroll
        for (int nt = 0; nt < 8; nt++) {
            int cb = n0 + wn * 64 + nt * 8;   // 8-group base (logical == physical)
            int c0 = cb + tig * 2;
            float v00 = (acc[mt][nt][0] + bias[c0])     * scale;
            float v01 = (acc[mt][nt][1] + bias[c0 + 1]) * scale;
            float v10 = (acc[mt][nt][2] + bias[c0])     * scale;
            float v11 = (acc[mt][nt][3] + bias[c0 + 1]) * scale;
            if (mode >= 1) {
                v00 = rtf(v00); v01 = rtf(v01);
                v10 = rtf(v10); v11 = rtf(v11);
            }
            if (mode >= 2) {   // permuted scatter (2x STG.32 per row)
                float* r0 = C + (size_t)row * ND + cb;
                float* r1 = C + (size_t)(row + 8) * ND + cb;
                r0[pe] = v00; r0[po] = v01;
                r1[pe] = v10; r1[po] = v11;
            } else {
                *(float2*)(C + (size_t)row * ND + c0)       = make_float2(v00, v01);
                *(float2*)(C + (size_t)(row + 8) * ND + c0) = make_float2(v10, v11);
            }
        }
    }
}

__global__ void __launch_bounds__(256, 2)
qkv_mma(const float* __restrict__ bq, const float* __restrict__ bk,
        const float* __restrict__ bv)
{
    if (blockIdx.z == 0)
        gemm_cp_body(g_x[0], g_wt[0], bq, SCALE, 3, g_q);  // round+perm+scale
    else if (blockIdx.z == 1)
        gemm_cp_body(g_x[1], g_wt[1], bk, 1.f, 2, g_k);    // round+perm
    else
        gemm_cp_body(g_x[2], g_wt[2], bv, 1.f, 1, g_v);    // round, plain layout
}

__global__ void __launch_bounds__(256, 2)
out_mma(const float* __restrict__ bo, float* __restrict__ out)
{
    gemm_cp_body(g_o, g_wt[3], bo, 1.f, 0, out);           // plain
}

// ---------------------------------------------------------------------------
// Flash attention: 128 threads, 64-query blocks, 32-key tiles.
// Q/K/S fragments via LDS.64 (k-pair layout); V plain with stride 72.
// ---------------------------------------------------------------------------
constexpr int AS = 72;
constexpr int Q_OFF = 0;             // 64 x 72
constexpr int K_OFF = 64 * AS;       // 32 x 72
constexpr int V_OFF = 96 * AS;       // 32 x 72
constexpr int S_OFF = 128 * AS;      // 64 x 72
constexpr int ATTN_SMEM = 192 * AS * 4;   // 55296 bytes

__global__ void __launch_bounds__(128) attn_mma()
{
    extern __shared__ float sm[];
    float* Qs  = sm + Q_OFF;
    float* Ks  = sm + K_OFF;
    float* Vs  = sm + V_OFF;
    float* Ssm = sm + S_OFF;
    __shared__ float mrow[64], lrow[64], frow[64];

    const int t   = threadIdx.x;
    const int wid = t >> 5;
    const int lid = t & 31;
    const int g   = lid >> 2;
    const int tig = lid & 3;
    const int q0  = blockIdx.x * 64;
    const int b   = blockIdx.y >> 3;
    const int h   = blockIdx.y & 7;
    const size_t base = (size_t)b * SEQ * ND + (size_t)h * DH;

    const int qrow = wid * 16 + g;
    const int pe = f8(2 * tig);
    const int po = f8(2 * tig + 1);

    // Q tile: 64 x 64, already scaled/rounded/permuted -> verbatim cp.async
    #pragma unroll
    for (int i = 0; i < 8; i++) {
        int idx = t + i * 128;          // 0..1023
        int r   = idx >> 4;             // 0..63
        int c4  = (idx & 15) << 2;
        cp16(smem_u32(&Qs[r * AS + c4]),
             g_q + base + (size_t)(q0 + r) * ND + c4);
    }
    if (t < 64) { mrow[t] = -1e30f; lrow[t] = 0.f; }

    float oacc[8][4] = {};

    for (int kt = 0; kt < 32; kt++) {
        const int k0 = kt * 32;

        // K (permuted layout) and V (plain) tiles: 32 x 64 each
        #pragma unroll
        for (int i = 0; i < 4; i++) {
            int idx = t + i * 128;      // 0..511
            int r   = idx >> 4;         // 0..31
            int c4  = (idx & 15) << 2;
            cp16(smem_u32(&Ks[r * AS + c4]),
                 g_k + base + (size_t)(k0 + r) * ND + c4);
            cp16(smem_u32(&Vs[r * AS + c4]),
                 g_v + base + (size_t)(k0 + r) * ND + c4);
        }
        CP_COMMIT();
        CP_WAIT(0);
        __syncthreads();

        // S = Q @ K^T : warp covers 16 q-rows x 32 keys
        float sfr[4][4] = {};
        #pragma unroll
        for (int ks = 0; ks < 8; ks++) {
            const int kk = ks * 8;
            uint32_t afr[4];
            float2 p0 = *(const float2*)&Qs[qrow * AS + kk + 2 * tig];
            float2 p1 = *(const float2*)&Qs[(qrow + 8) * AS + kk + 2 * tig];
            afr[0] = __float_as_uint(p0.x);
            afr[1] = __float_as_uint(p1.x);
            afr[2] = __float_as_uint(p0.y);
            afr[3] = __float_as_uint(p1.y);
            #pragma unroll
            for (int nt = 0; nt < 4; nt++) {
                uint32_t bfr[2];
                float2 pb = *(const float2*)&Ks[(nt * 8 + g) * AS + kk + 2 * tig];
                bfr[0] = __float_as_uint(pb.x);
                bfr[1] = __float_as_uint(pb.y);
                mma_tf32(sfr[nt], afr, bfr);
            }
        }
        // Store S with key positions permuted (so P fragments pair for LDS.64)
        #pragma unroll
        for (int nt = 0; nt < 4; nt++) {
            float* r0 = &Ssm[qrow * AS + nt * 8];
            float* r1 = &Ssm[(qrow + 8) * AS + nt * 8];
            r0[pe] = sfr[nt][0]; r0[po] = sfr[nt][1];
            r1[pe] = sfr[nt][2]; r1[po] = sfr[nt][3];
        }
        __syncthreads();

        // Parallel online softmax: 2 threads per row, 16 keys each
        {
            int row  = t >> 1;
            int half = t & 1;
            float* p = &Ssm[row * AS + half * 16];
            float mx = -1e30f;
            #pragma unroll
            for (int j = 0; j < 16; j++) mx = fmaxf(mx, p[j]);
            mx = fmaxf(mx, __shfl_xor_sync(0xFFFFFFFF, mx, 1));
            float mo = mrow[row];
            float nm = fmaxf(mo, mx);
            float f  = __expf(mo - nm);
            float sum = 0.f;
            #pragma unroll
            for (int j = 0; j < 16; j++) {
                float e = __expf(p[j] - nm);
                sum += e;
                p[j] = rtf(e);
            }
            sum += __shfl_xor_sync(0xFFFFFFFF, sum, 1);
            if (half == 0) {
                mrow[row] = nm;
                lrow[row] = lrow[row] * f + sum;
                frow[row] = f;
            }
        }
        __syncthreads();

        // Rescale running O, accumulate P @ V (warp: 16 q x 64 d)
        float f0 = frow[qrow];
        float f1 = frow[qrow + 8];
        #pragma unroll
        for (int nt = 0; nt < 8; nt++) {
            oacc[nt][0] *= f0;  oacc[nt][1] *= f0;
            oacc[nt][2] *= f1;  oacc[nt][3] *= f1;
        }
        #pragma unroll
        for (int ks = 0; ks < 4; ks++) {
            const int kk = ks * 8;
            uint32_t afr[4];
            float2 p0 = *(const float2*)&Ssm[qrow * AS + kk + 2 * tig];
            float2 p1 = *(const float2*)&Ssm[(qrow + 8) * AS + kk + 2 * tig];
            afr[0] = __float_as_uint(p0.x);
            afr[1] = __float_as_uint(p1.x);
            afr[2] = __float_as_uint(p0.y);
            afr[3] = __float_as_uint(p1.y);
            #pragma unroll
            for (int nt = 0; nt < 8; nt++) {
                uint32_t bfr[2];
                int rb = (kk + tig) * AS + nt * 8 + g;
                bfr[0] = __float_as_uint(Vs[rb]);
                bfr[1] = __float_as_uint(Vs[rb + 4 * AS]);
                mma_tf32(oacc[nt], afr, bfr);
            }
        }
        __syncthreads();
    }

    // Normalize, round, d-permute, write O
    float inv0 = 1.f / lrow[qrow];
    float inv1 = 1.f / lrow[qrow + 8];
    #pragma unroll
    for (int nt = 0; nt < 8; nt++) {
        float* r0 = g_o + base + (size_t)(q0 + qrow) * ND + nt * 8;
        float* r1 = g_o + base + (size_t)(q0 + qrow + 8) * ND + nt * 8;
        r0[pe] = rtf(oacc[nt][0] * inv0);
        r0[po] = rtf(oacc[nt][1] * inv0);
        r1[pe] = rtf(oacc[nt][2] * inv1);
        r1[po] = rtf(oacc[nt][3] * inv1);
    }
}

// ---------------------------------------------------------------------------
extern "C" void kernel_launch(void* const* d_in, const int* in_sizes, int n_in,
                              void* d_out, int out_size)
{
    const float* q  = (const float*)d_in[0];
    const float* k  = (const float*)d_in[1];
    const float* v  = (const float*)d_in[2];
    const float* Wq = (const float*)d_in[3];
    const float* bq = (const float*)d_in[4];
    const float* Wk = (const float*)d_in[5];
    const float* bk = (const float*)d_in[6];
    const float* Wv = (const float*)d_in[7];
    const float* bv = (const float*)d_in[8];
    const float* Wo = (const float*)d_in[9];
    const float* bo = (const float*)d_in[10];

    static bool attr_done = false;
    if (!attr_done) {
        cudaFuncSetAttribute(qkv_mma, cudaFuncAttributeMaxDynamicSharedMemorySize, GEMM_SMEM);
        cudaFuncSetAttribute(out_mma, cudaFuncAttributeMaxDynamicSharedMemorySize, GEMM_SMEM);
        cudaFuncSetAttribute(attn_mma, cudaFuncAttributeMaxDynamicSharedMemorySize, ATTN_SMEM);
        attr_done = true;
    }

    round_inputs<<<dim3(512, 3), 256>>>(q, k, v);
    transposeW<<<dim3(16, 16, 4), dim3(32, 8)>>>(Wq, Wk, Wv, Wo);
    qkv_mma<<<dim3(ND / 128, Mrows / 128, 3), 256, GEMM_SMEM>>>(bq, bk, bv);
    attn_mma<<<dim3(SEQ / 64, Bb * Hh), 128, ATTN_SMEM>>>();
    out_mma<<<dim3(ND / 128, Mrows / 128), 256, GEMM_SMEM>>>(bo, (float*)d_out);
}

// round 6
// speedup vs baseline: 1.3713x; 1.1523x over previous
#include <cuda_runtime.h>
#include <cstdint>
#include <math.h>

// Problem constants
constexpr int Bb  = 8;
constexpr int SEQ = 1024;
constexpr int Hh  = 8;
constexpr int DH  = 64;
constexpr int Mrows = Bb * SEQ;   // 8192
constexpr int KD = 512;
constexpr int ND = 512;
constexpr float SCALE = 0.04419417382415922f;   // 1/sqrt(512)

// Scratch (device globals: allocation-free rule)
__device__ float g_x[3][Mrows * ND];   // tf32-rounded, k-pair-permuted inputs
__device__ float g_q[Mrows * ND];      // rounded, scaled, d-permuted Q proj
__device__ float g_k[Mrows * ND];      // rounded, d-permuted K proj
__device__ float g_v[Mrows * ND];      // rounded V proj (plain layout)
__device__ float g_o[Mrows * ND];      // rounded, d-permuted attention output
__device__ float g_wt[4][KD * ND];     // transposed, rounded, k-permuted weights

// ---------------------------------------------------------------------------
// Helpers
// ---------------------------------------------------------------------------
__device__ __forceinline__ uint32_t f2tf32(float x) {
    uint32_t r;
    asm("cvt.rna.tf32.f32 %0, %1;" : "=r"(r) : "f"(x));
    return r;
}
__device__ __forceinline__ float rtf(float x) {
    return __uint_as_float(f2tf32(x));
}

// Position of k-slot j within its 8-group: layout [0,4,1,5,2,6,3,7]
__device__ __forceinline__ int f8(int j) {
    return ((j & 3) << 1) | ((j >> 2) & 1);
}

__device__ __forceinline__ void mma_tf32(float c[4], const uint32_t a[4],
                                         const uint32_t b[2]) {
    asm volatile(
        "mma.sync.aligned.m16n8k8.row.col.f32.tf32.tf32.f32 "
        "{%0,%1,%2,%3}, {%4,%5,%6,%7}, {%8,%9}, {%0,%1,%2,%3};"
        : "+f"(c[0]), "+f"(c[1]), "+f"(c[2]), "+f"(c[3])
        : "r"(a[0]), "r"(a[1]), "r"(a[2]), "r"(a[3]),
          "r"(b[0]), "r"(b[1]));
}

__device__ __forceinline__ uint32_t smem_u32(const void* p) {
    uint32_t a;
    asm("{ .reg .u64 t; cvta.to.shared.u64 t, %1; cvt.u32.u64 %0, t; }"
        : "=r"(a) : "l"(p));
    return a;
}

__device__ __forceinline__ void cp16(uint32_t dst, const void* src) {
    asm volatile("cp.async.cg.shared.global [%0], [%1], 16;"
                 :: "r"(dst), "l"(src) : "memory");
}
#define CP_COMMIT() asm volatile("cp.async.commit_group;" ::: "memory")
#define CP_WAIT(n)  asm volatile("cp.async.wait_group %0;" :: "n"(n) : "memory")

// ---------------------------------------------------------------------------
// Prep: round + k-pair-permute input activations into g_x
// ---------------------------------------------------------------------------
__global__ void round_inputs(const float* __restrict__ q,
                             const float* __restrict__ k,
                             const float* __restrict__ v)
{
    const float* src = (blockIdx.y == 0) ? q : (blockIdx.y == 1) ? k : v;
    float* dst = g_x[blockIdx.y];
    const int total = Mrows * ND / 8;
    for (int i = blockIdx.x * blockDim.x + threadIdx.x; i < total;
         i += gridDim.x * blockDim.x) {
        const float4 a = ((const float4*)src)[i * 2];
        const float4 b = ((const float4*)src)[i * 2 + 1];
        float4 o0, o1;   // positions [s0,s4,s1,s5] and [s2,s6,s3,s7]
        o0.x = rtf(a.x); o0.y = rtf(b.x); o0.z = rtf(a.y); o0.w = rtf(b.y);
        o1.x = rtf(a.z); o1.y = rtf(b.z); o1.z = rtf(a.w); o1.w = rtf(b.w);
        ((float4*)dst)[i * 2]     = o0;
        ((float4*)dst)[i * 2 + 1] = o1;
    }
}

// ---------------------------------------------------------------------------
// Weight transpose + round + k-permute: Wt[n][perm(k)] = round(W[k][n])
// ---------------------------------------------------------------------------
__global__ void transposeW(const float* __restrict__ Wq,
                           const float* __restrict__ Wk,
                           const float* __restrict__ Wv,
                           const float* __restrict__ Wo)
{
    __shared__ float tile[32][33];
    const float* src;
    switch (blockIdx.z) {
        case 0: src = Wq; break;
        case 1: src = Wk; break;
        case 2: src = Wv; break;
        default: src = Wo; break;
    }
    float* dst = g_wt[blockIdx.z];

    int x = blockIdx.x * 32 + threadIdx.x;
    int y = blockIdx.y * 32 + threadIdx.y;
    #pragma unroll
    for (int j = 0; j < 32; j += 8)
        tile[threadIdx.y + j][threadIdx.x] = rtf(src[(size_t)(y + j) * ND + x]);
    __syncthreads();
    int x2 = blockIdx.y * 32 + threadIdx.x;          // k index
    int x2p = (x2 & ~7) | f8(x2 & 7);                // permuted k position
    int y2 = blockIdx.x * 32 + threadIdx.y;          // n index
    #pragma unroll
    for (int j = 0; j < 32; j += 8)
        dst[(size_t)(y2 + j) * KD + x2p] = tile[threadIdx.x][threadIdx.y + j];
}

// ---------------------------------------------------------------------------
// tf32 mma GEMM (unchanged from round 5): 2-stage cp.async, LDS.64 fragments.
// Epilogue modes: 0 plain, 1 round, 2 round+perm, 3 round+perm+scale
// ---------------------------------------------------------------------------
constexpr int GS = 40;
constexpr int GEMM_STAGE = 128 * GS;
constexpr int GEMM_SMEM  = 4 * GEMM_STAGE * 4; // 81920 bytes

__device__ __forceinline__ void gemm_cp_body(const float* __restrict__ A,
                                             const float* __restrict__ Bt,
                                             const float* __restrict__ bias,
                                             float scale, int mode,
                                             float* __restrict__ C)
{
    extern __shared__ float sm[];
    float* sAp[2] = { sm,              sm + 2 * GEMM_STAGE };
    float* sBp[2] = { sm + GEMM_STAGE, sm + 3 * GEMM_STAGE };

    const int t   = threadIdx.x;
    const int wid = t >> 5;
    const int lid = t & 31;
    const int g   = lid >> 2;
    const int tig = lid & 3;
    const int wm  = wid & 3;
    const int wn  = wid >> 2;
    const int m0  = blockIdx.y * 128;
    const int n0  = blockIdx.x * 128;

    float acc[2][8][4] = {};

    auto load_stage = [&](int s, int k0) {
        #pragma unroll
        for (int i = 0; i < 4; i++) {
            int idx = t + i * 256;
            int r   = idx >> 3;
            int c4  = (idx & 7) << 2;
            cp16(smem_u32(&sAp[s][r * GS + c4]),
                 A + (size_t)(m0 + r) * KD + k0 + c4);
            cp16(smem_u32(&sBp[s][r * GS + c4]),
                 Bt + (size_t)(n0 + r) * KD + k0 + c4);
        }
        CP_COMMIT();
    };

    load_stage(0, 0);

    for (int it = 0; it < 16; it++) {
        if (it < 15) { load_stage((it + 1) & 1, (it + 1) * 32); CP_WAIT(1); }
        else         { CP_WAIT(0); }
        __syncthreads();

        const float* sA = sAp[it & 1];
        const float* sB = sBp[it & 1];

        #pragma unroll
        for (int ks = 0; ks < 4; ks++) {
            const int kk = ks * 8;
            uint32_t afr[2][4];
            #pragma unroll
            for (int mt = 0; mt < 2; mt++) {
                int rowa = wm * 32 + mt * 16 + g;
                float2 p0 = *(const float2*)&sA[rowa * GS + kk + 2 * tig];
                float2 p1 = *(const float2*)&sA[(rowa + 8) * GS + kk + 2 * tig];
                afr[mt][0] = __float_as_uint(p0.x);
                afr[mt][1] = __float_as_uint(p1.x);
                afr[mt][2] = __float_as_uint(p0.y);
                afr[mt][3] = __float_as_uint(p1.y);
            }
            uint32_t bfr[8][2];
            #pragma unroll
            for (int nt = 0; nt < 8; nt++) {
                float2 pb = *(const float2*)&sB[(wn * 64 + nt * 8 + g) * GS
                                                + kk + 2 * tig];
                bfr[nt][0] = __float_as_uint(pb.x);
                bfr[nt][1] = __float_as_uint(pb.y);
            }
            #pragma unroll
            for (int mt = 0; mt < 2; mt++)
                #pragma unroll
                for (int nt = 0; nt < 8; nt++)
                    mma_tf32(acc[mt][nt], afr[mt], bfr[nt]);
        }
        __syncthreads();
    }

    const int pe = f8(2 * tig);
    const int po = f8(2 * tig + 1);
    #pragma unroll
    for (int mt = 0; mt < 2; mt++) {
        int row = m0 + wm * 32 + mt * 16 + g;
        #pragma unroll
        for (int nt = 0; nt < 8; nt++) {
            int cb = n0 + wn * 64 + nt * 8;
            int c0 = cb + tig * 2;
            float v00 = (acc[mt][nt][0] + bias[c0])     * scale;
            float v01 = (acc[mt][nt][1] + bias[c0 + 1]) * scale;
            float v10 = (acc[mt][nt][2] + bias[c0])     * scale;
            float v11 = (acc[mt][nt][3] + bias[c0 + 1]) * scale;
            if (mode >= 1) {
                v00 = rtf(v00); v01 = rtf(v01);
                v10 = rtf(v10); v11 = rtf(v11);
            }
            if (mode >= 2) {
                float* r0 = C + (size_t)row * ND + cb;
                float* r1 = C + (size_t)(row + 8) * ND + cb;
                r0[pe] = v00; r0[po] = v01;
                r1[pe] = v10; r1[po] = v11;
            } else {
                *(float2*)(C + (size_t)row * ND + c0)       = make_float2(v00, v01);
                *(float2*)(C + (size_t)(row + 8) * ND + c0) = make_float2(v10, v11);
            }
        }
    }
}

__global__ void __launch_bounds__(256, 2)
qkv_mma(const float* __restrict__ bq, const float* __restrict__ bk,
        const float* __restrict__ bv)
{
    if (blockIdx.z == 0)
        gemm_cp_body(g_x[0], g_wt[0], bq, SCALE, 3, g_q);  // round+perm+scale
    else if (blockIdx.z == 1)
        gemm_cp_body(g_x[1], g_wt[1], bk, 1.f, 2, g_k);    // round+perm
    else
        gemm_cp_body(g_x[2], g_wt[2], bv, 1.f, 1, g_v);    // round, plain
}

__global__ void __launch_bounds__(256, 2)
out_mma(const float* __restrict__ bo, float* __restrict__ out)
{
    gemm_cp_body(g_o, g_wt[3], bo, 1.f, 0, out);           // plain
}

// ---------------------------------------------------------------------------
// Flash attention, register-resident S/P (FA2 style).
// 128 threads, 64-query blocks, 32-key tiles, double-buffered K/V.
// K tile rows stored key-permuted so S C-fragments == P A-fragments.
// ---------------------------------------------------------------------------
constexpr int AS = 72;
constexpr int KV_STAGE = 32 * AS;              // floats per K (or V) tile
constexpr int ATTN_SMEM = 4 * KV_STAGE * 4;    // K0,V0,K1,V1 = 36864 bytes

__global__ void __launch_bounds__(128) attn_mma()
{
    extern __shared__ float sm[];
    float* Kb[2] = { sm,            sm + 2 * KV_STAGE };
    float* Vb[2] = { sm + KV_STAGE, sm + 3 * KV_STAGE };

    const int t   = threadIdx.x;
    const int wid = t >> 5;
    const int lid = t & 31;
    const int g   = lid >> 2;
    const int tig = lid & 3;
    const int q0  = blockIdx.x * 64;
    const int b   = blockIdx.y >> 3;
    const int h   = blockIdx.y & 7;
    const size_t base = (size_t)b * SEQ * ND + (size_t)h * DH;

    const int qrow = wid * 16 + g;

    // Q fragments straight from gmem (pre-scaled/rounded/d-permuted)
    uint32_t qf[8][4];
    {
        const float* qp0 = g_q + base + (size_t)(q0 + qrow) * ND;
        const float* qp1 = qp0 + 8 * ND;
        #pragma unroll
        for (int ks = 0; ks < 8; ks++) {
            float2 p0 = *(const float2*)(qp0 + ks * 8 + 2 * tig);
            float2 p1 = *(const float2*)(qp1 + ks * 8 + 2 * tig);
            qf[ks][0] = __float_as_uint(p0.x);
            qf[ks][1] = __float_as_uint(p1.x);
            qf[ks][2] = __float_as_uint(p0.y);
            qf[ks][3] = __float_as_uint(p1.y);
        }
    }

    auto load_kv = [&](int s, int k0) {
        #pragma unroll
        for (int i = 0; i < 4; i++) {
            int idx = t + i * 128;      // 0..511
            int r   = idx >> 4;         // key row 0..31
            int c4  = (idx & 15) << 2;
            int rp  = (r & ~7) | f8(r & 7);   // permuted key position (K only)
            cp16(smem_u32(&Kb[s][rp * AS + c4]),
                 g_k + base + (size_t)(k0 + r) * ND + c4);
            cp16(smem_u32(&Vb[s][r * AS + c4]),
                 g_v + base + (size_t)(k0 + r) * ND + c4);
        }
        CP_COMMIT();
    };
    load_kv(0, 0);

    float m0 = -1e30f, m1 = -1e30f, l0 = 0.f, l1 = 0.f;
    float oacc[8][4] = {};

    for (int kt = 0; kt < 32; kt++) {
        if (kt < 31) { load_kv((kt + 1) & 1, (kt + 1) * 32); CP_WAIT(1); }
        else         { CP_WAIT(0); }
        __syncthreads();

        const float* Ks = Kb[kt & 1];
        const float* Vs = Vb[kt & 1];

        // S = Q @ K^T : sfr[nt] covers physical key cols [8nt, 8nt+8)
        // slot meaning (logical keys): [0]=8nt+tig(row g), [1]=8nt+tig+4(row g),
        //                              [2],[3] = same cols, row g+8
        float sfr[4][4] = {};
        #pragma unroll
        for (int ks = 0; ks < 8; ks++) {
            const int kk = ks * 8;
            #pragma unroll
            for (int nt = 0; nt < 4; nt++) {
                uint32_t bfr[2];
                float2 pb = *(const float2*)&Ks[(nt * 8 + g) * AS + kk + 2 * tig];
                bfr[0] = __float_as_uint(pb.x);
                bfr[1] = __float_as_uint(pb.y);
                mma_tf32(sfr[nt], qf[ks], bfr);
            }
        }

        // Register softmax: rows g (slots 0,1) and g+8 (slots 2,3), quad reduce
        float mx0 = -1e30f, mx1 = -1e30f;
        #pragma unroll
        for (int nt = 0; nt < 4; nt++) {
            mx0 = fmaxf(mx0, fmaxf(sfr[nt][0], sfr[nt][1]));
            mx1 = fmaxf(mx1, fmaxf(sfr[nt][2], sfr[nt][3]));
        }
        mx0 = fmaxf(mx0, __shfl_xor_sync(0xFFFFFFFF, mx0, 1));
        mx0 = fmaxf(mx0, __shfl_xor_sync(0xFFFFFFFF, mx0, 2));
        mx1 = fmaxf(mx1, __shfl_xor_sync(0xFFFFFFFF, mx1, 1));
        mx1 = fmaxf(mx1, __shfl_xor_sync(0xFFFFFFFF, mx1, 2));

        float nm0 = fmaxf(m0, mx0);
        float nm1 = fmaxf(m1, mx1);
        float f0  = __expf(m0 - nm0);
        float f1  = __expf(m1 - nm1);
        float sum0 = 0.f, sum1 = 0.f;
        #pragma unroll
        for (int nt = 0; nt < 4; nt++) {
            sfr[nt][0] = __expf(sfr[nt][0] - nm0);
            sfr[nt][1] = __expf(sfr[nt][1] - nm0);
            sfr[nt][2] = __expf(sfr[nt][2] - nm1);
            sfr[nt][3] = __expf(sfr[nt][3] - nm1);
            sum0 += sfr[nt][0] + sfr[nt][1];
            sum1 += sfr[nt][2] + sfr[nt][3];
        }
        sum0 += __shfl_xor_sync(0xFFFFFFFF, sum0, 1);
        sum0 += __shfl_xor_sync(0xFFFFFFFF, sum0, 2);
        sum1 += __shfl_xor_sync(0xFFFFFFFF, sum1, 1);
        sum1 += __shfl_xor_sync(0xFFFFFFFF, sum1, 2);
        l0 = l0 * f0 + sum0;  m0 = nm0;
        l1 = l1 * f1 + sum1;  m1 = nm1;

        // Rescale running O
        #pragma unroll
        for (int nt = 0; nt < 8; nt++) {
            oacc[nt][0] *= f0;  oacc[nt][1] *= f0;
            oacc[nt][2] *= f1;  oacc[nt][3] *= f1;
        }

        // P @ V : P A-fragments come straight from sfr (tf32-rounded)
        #pragma unroll
        for (int ks = 0; ks < 4; ks++) {
            uint32_t afr[4];
            afr[0] = f2tf32(sfr[ks][0]);   // P[g][8ks+tig]
            afr[1] = f2tf32(sfr[ks][2]);   // P[g+8][8ks+tig]
            afr[2] = f2tf32(sfr[ks][1]);   // P[g][8ks+tig+4]
            afr[3] = f2tf32(sfr[ks][3]);   // P[g+8][8ks+tig+4]
            const int kk = ks * 8;
            #pragma unroll
            for (int nt = 0; nt < 8; nt++) {
                uint32_t bfr[2];
                int rb = (kk + tig) * AS + nt * 8 + g;
                bfr[0] = __float_as_uint(Vs[rb]);
                bfr[1] = __float_as_uint(Vs[rb + 4 * AS]);
                mma_tf32(oacc[nt], afr, bfr);
            }
        }
        __syncthreads();
    }

    // Normalize, round, d-permute, write O
    const int pe = f8(2 * tig);
    const int po = f8(2 * tig + 1);
    float inv0 = 1.f / l0;
    float inv1 = 1.f / l1;
    #pragma unroll
    for (int nt = 0; nt < 8; nt++) {
        float* r0 = g_o + base + (size_t)(q0 + qrow) * ND + nt * 8;
        float* r1 = g_o + base + (size_t)(q0 + qrow + 8) * ND + nt * 8;
        r0[pe] = rtf(oacc[nt][0] * inv0);
        r0[po] = rtf(oacc[nt][1] * inv0);
        r1[pe] = rtf(oacc[nt][2] * inv1);
        r1[po] = rtf(oacc[nt][3] * inv1);
    }
}

// ---------------------------------------------------------------------------
extern "C" void kernel_launch(void* const* d_in, const int* in_sizes, int n_in,
                              void* d_out, int out_size)
{
    const float* q  = (const float*)d_in[0];
    const float* k  = (const float*)d_in[1];
    const float* v  = (const float*)d_in[2];
    const float* Wq = (const float*)d_in[3];
    const float* bq = (const float*)d_in[4];
    const float* Wk = (const float*)d_in[5];
    const float* bk = (const float*)d_in[6];
    const float* Wv = (const float*)d_in[7];
    const float* bv = (const float*)d_in[8];
    const float* Wo = (const float*)d_in[9];
    const float* bo = (const float*)d_in[10];

    static bool attr_done = false;
    if (!attr_done) {
        cudaFuncSetAttribute(qkv_mma, cudaFuncAttributeMaxDynamicSharedMemorySize, GEMM_SMEM);
        cudaFuncSetAttribute(out_mma, cudaFuncAttributeMaxDynamicSharedMemorySize, GEMM_SMEM);
        cudaFuncSetAttribute(attn_mma, cudaFuncAttributeMaxDynamicSharedMemorySize, ATTN_SMEM);
        attr_done = true;
    }

    round_inputs<<<dim3(512, 3), 256>>>(q, k, v);
    transposeW<<<dim3(16, 16, 4), dim3(32, 8)>>>(Wq, Wk, Wv, Wo);
    qkv_mma<<<dim3(ND / 128, Mrows / 128, 3), 256, GEMM_SMEM>>>(bq, bk, bv);
    attn_mma<<<dim3(SEQ / 64, Bb * Hh), 128, ATTN_SMEM>>>();
    out_mma<<<dim3(ND / 128, Mrows / 128), 256, GEMM_SMEM>>>(bo, (float*)d_out);
}

// round 7
// speedup vs baseline: 1.4104x; 1.0285x over previous
#include <cuda_runtime.h>
#include <cstdint>
#include <math.h>

// Problem constants
constexpr int Bb  = 8;
constexpr int SEQ = 1024;
constexpr int Hh  = 8;
constexpr int DH  = 64;
constexpr int Mrows = Bb * SEQ;   // 8192
constexpr int KD = 512;
constexpr int ND = 512;
constexpr float SCALE  = 0.04419417382415922f;    // 1/sqrt(512)
constexpr float SCALE2 = 0.06376143939677731f;    // SCALE * log2(e)

// Scratch (device globals: allocation-free rule)
__device__ float g_x[3][Mrows * ND];   // tf32-rounded, k-pair-permuted inputs
__device__ float g_q[Mrows * ND];      // rounded, scaled(log2e), d-permuted Q
__device__ float g_k[Mrows * ND];      // rounded, d-permuted K proj
__device__ float g_vt[Mrows * ND];     // rounded V^T: [b,h,dh,perm(seq)]
__device__ float g_o[Mrows * ND];      // rounded, d-permuted attention output
__device__ float g_wt[4][KD * ND];     // transposed, rounded, k-permuted weights

// ---------------------------------------------------------------------------
// Helpers
// ---------------------------------------------------------------------------
__device__ __forceinline__ uint32_t f2tf32(float x) {
    uint32_t r;
    asm("cvt.rna.tf32.f32 %0, %1;" : "=r"(r) : "f"(x));
    return r;
}
__device__ __forceinline__ float rtf(float x) {
    return __uint_as_float(f2tf32(x));
}

// Position of k-slot j within its 8-group: layout [0,4,1,5,2,6,3,7]
__device__ __forceinline__ int f8(int j) {
    return ((j & 3) << 1) | ((j >> 2) & 1);
}

__device__ __forceinline__ void mma_tf32(float c[4], const uint32_t a[4],
                                         const uint32_t b[2]) {
    asm volatile(
        "mma.sync.aligned.m16n8k8.row.col.f32.tf32.tf32.f32 "
        "{%0,%1,%2,%3}, {%4,%5,%6,%7}, {%8,%9}, {%0,%1,%2,%3};"
        : "+f"(c[0]), "+f"(c[1]), "+f"(c[2]), "+f"(c[3])
        : "r"(a[0]), "r"(a[1]), "r"(a[2]), "r"(a[3]),
          "r"(b[0]), "r"(b[1]));
}

__device__ __forceinline__ uint32_t smem_u32(const void* p) {
    uint32_t a;
    asm("{ .reg .u64 t; cvta.to.shared.u64 t, %1; cvt.u32.u64 %0, t; }"
        : "=r"(a) : "l"(p));
    return a;
}

__device__ __forceinline__ void cp16(uint32_t dst, const void* src) {
    asm volatile("cp.async.cg.shared.global [%0], [%1], 16;"
                 :: "r"(dst), "l"(src) : "memory");
}
#define CP_COMMIT() asm volatile("cp.async.commit_group;" ::: "memory")
#define CP_WAIT(n)  asm volatile("cp.async.wait_group %0;" :: "n"(n) : "memory")

// ---------------------------------------------------------------------------
// Prep: round + k-pair-permute input activations into g_x
// ---------------------------------------------------------------------------
__global__ void round_inputs(const float* __restrict__ q,
                             const float* __restrict__ k,
                             const float* __restrict__ v)
{
    const float* src = (blockIdx.y == 0) ? q : (blockIdx.y == 1) ? k : v;
    float* dst = g_x[blockIdx.y];
    const int total = Mrows * ND / 8;
    for (int i = blockIdx.x * blockDim.x + threadIdx.x; i < total;
         i += gridDim.x * blockDim.x) {
        const float4 a = ((const float4*)src)[i * 2];
        const float4 b = ((const float4*)src)[i * 2 + 1];
        float4 o0, o1;   // positions [s0,s4,s1,s5] and [s2,s6,s3,s7]
        o0.x = rtf(a.x); o0.y = rtf(b.x); o0.z = rtf(a.y); o0.w = rtf(b.y);
        o1.x = rtf(a.z); o1.y = rtf(b.z); o1.z = rtf(a.w); o1.w = rtf(b.w);
        ((float4*)dst)[i * 2]     = o0;
        ((float4*)dst)[i * 2 + 1] = o1;
    }
}

// ---------------------------------------------------------------------------
// Weight transpose + round + k-permute: Wt[n][perm(k)] = round(W[k][n])
// ---------------------------------------------------------------------------
__global__ void transposeW(const float* __restrict__ Wq,
                           const float* __restrict__ Wk,
                           const float* __restrict__ Wv,
                           const float* __restrict__ Wo)
{
    __shared__ float tile[32][33];
    const float* src;
    switch (blockIdx.z) {
        case 0: src = Wq; break;
        case 1: src = Wk; break;
        case 2: src = Wv; break;
        default: src = Wo; break;
    }
    float* dst = g_wt[blockIdx.z];

    int x = blockIdx.x * 32 + threadIdx.x;
    int y = blockIdx.y * 32 + threadIdx.y;
    #pragma unroll
    for (int j = 0; j < 32; j += 8)
        tile[threadIdx.y + j][threadIdx.x] = rtf(src[(size_t)(y + j) * ND + x]);
    __syncthreads();
    int x2 = blockIdx.y * 32 + threadIdx.x;          // k index
    int x2p = (x2 & ~7) | f8(x2 & 7);                // permuted k position
    int y2 = blockIdx.x * 32 + threadIdx.y;          // n index
    #pragma unroll
    for (int j = 0; j < 32; j += 8)
        dst[(size_t)(y2 + j) * KD + x2p] = tile[threadIdx.x][threadIdx.y + j];
}

// ---------------------------------------------------------------------------
// tf32 mma GEMM: 2-stage cp.async, LDS.64 fragments.
// Epilogue modes: 0 plain, 1 round, 2 round+perm, 3 round+perm+scale,
//                 4 round + transposed V write (g_vt[b,h,dh,perm(s)])
// ---------------------------------------------------------------------------
constexpr int GS = 40;
constexpr int GEMM_STAGE = 128 * GS;
constexpr int GEMM_SMEM  = 4 * GEMM_STAGE * 4; // 81920 bytes

__device__ __forceinline__ void gemm_cp_body(const float* __restrict__ A,
                                             const float* __restrict__ Bt,
                                             const float* __restrict__ bias,
                                             float scale, int mode,
                                             float* __restrict__ C)
{
    extern __shared__ float sm[];
    float* sAp[2] = { sm,              sm + 2 * GEMM_STAGE };
    float* sBp[2] = { sm + GEMM_STAGE, sm + 3 * GEMM_STAGE };

    const int t   = threadIdx.x;
    const int wid = t >> 5;
    const int lid = t & 31;
    const int g   = lid >> 2;
    const int tig = lid & 3;
    const int wm  = wid & 3;
    const int wn  = wid >> 2;
    const int m0  = blockIdx.y * 128;
    const int n0  = blockIdx.x * 128;

    float acc[2][8][4] = {};

    auto load_stage = [&](int s, int k0) {
        #pragma unroll
        for (int i = 0; i < 4; i++) {
            int idx = t + i * 256;
            int r   = idx >> 3;
            int c4  = (idx & 7) << 2;
            cp16(smem_u32(&sAp[s][r * GS + c4]),
                 A + (size_t)(m0 + r) * KD + k0 + c4);
            cp16(smem_u32(&sBp[s][r * GS + c4]),
                 Bt + (size_t)(n0 + r) * KD + k0 + c4);
        }
        CP_COMMIT();
    };

    load_stage(0, 0);

    for (int it = 0; it < 16; it++) {
        if (it < 15) { load_stage((it + 1) & 1, (it + 1) * 32); CP_WAIT(1); }
        else         { CP_WAIT(0); }
        __syncthreads();

        const float* sA = sAp[it & 1];
        const float* sB = sBp[it & 1];

        #pragma unroll
        for (int ks = 0; ks < 4; ks++) {
            const int kk = ks * 8;
            uint32_t afr[2][4];
            #pragma unroll
            for (int mt = 0; mt < 2; mt++) {
                int rowa = wm * 32 + mt * 16 + g;
                float2 p0 = *(const float2*)&sA[rowa * GS + kk + 2 * tig];
                float2 p1 = *(const float2*)&sA[(rowa + 8) * GS + kk + 2 * tig];
                afr[mt][0] = __float_as_uint(p0.x);
                afr[mt][1] = __float_as_uint(p1.x);
                afr[mt][2] = __float_as_uint(p0.y);
                afr[mt][3] = __float_as_uint(p1.y);
            }
            uint32_t bfr[8][2];
            #pragma unroll
            for (int nt = 0; nt < 8; nt++) {
                float2 pb = *(const float2*)&sB[(wn * 64 + nt * 8 + g) * GS
                                                + kk + 2 * tig];
                bfr[nt][0] = __float_as_uint(pb.x);
                bfr[nt][1] = __float_as_uint(pb.y);
            }
            #pragma unroll
            for (int mt = 0; mt < 2; mt++)
                #pragma unroll
                for (int nt = 0; nt < 8; nt++)
                    mma_tf32(acc[mt][nt], afr[mt], bfr[nt]);
        }
        __syncthreads();
    }

    const int pe = f8(2 * tig);
    const int po = f8(2 * tig + 1);
    #pragma unroll
    for (int mt = 0; mt < 2; mt++) {
        int row = m0 + wm * 32 + mt * 16 + g;
        #pragma unroll
        for (int nt = 0; nt < 8; nt++) {
            int cb = n0 + wn * 64 + nt * 8;
            int c0 = cb + tig * 2;
            float v00 = (acc[mt][nt][0] + bias[c0])     * scale;
            float v01 = (acc[mt][nt][1] + bias[c0 + 1]) * scale;
            float v10 = (acc[mt][nt][2] + bias[c0])     * scale;
            float v11 = (acc[mt][nt][3] + bias[c0 + 1]) * scale;
            if (mode >= 1) {
                v00 = rtf(v00); v01 = rtf(v01);
                v10 = rtf(v10); v11 = rtf(v11);
            }
            if (mode == 4) {
                // Transposed V write: vt[((b*8+h)*64+dh)*1024 + perm(s)]
                int b0 = row >> 10;
                int s0 = row & 1023;
                int s0p = (s0 & ~7) | f8(s0 & 7);
                int s1p = ((s0 + 8) & ~7) | f8((s0 + 8) & 7);
                int h  = c0 >> 6;
                int dh0 = c0 & 63;
                float* vt = C + (size_t)((b0 * 8 + h) * 64) * SEQ;
                vt[(size_t)dh0 * SEQ + s0p]       = v00;
                vt[(size_t)(dh0 + 1) * SEQ + s0p] = v01;
                vt[(size_t)dh0 * SEQ + s1p]       = v10;
                vt[(size_t)(dh0 + 1) * SEQ + s1p] = v11;
            } else if (mode >= 2) {
                float* r0 = C + (size_t)row * ND + cb;
                float* r1 = C + (size_t)(row + 8) * ND + cb;
                r0[pe] = v00; r0[po] = v01;
                r1[pe] = v10; r1[po] = v11;
            } else {
                *(float2*)(C + (size_t)row * ND + c0)       = make_float2(v00, v01);
                *(float2*)(C + (size_t)(row + 8) * ND + c0) = make_float2(v10, v11);
            }
        }
    }
}

__global__ void __launch_bounds__(256, 2)
qkv_mma(const float* __restrict__ bq, const float* __restrict__ bk,
        const float* __restrict__ bv)
{
    if (blockIdx.z == 0)
        gemm_cp_body(g_x[0], g_wt[0], bq, SCALE2, 3, g_q);  // round+perm+log2e scale
    else if (blockIdx.z == 1)
        gemm_cp_body(g_x[1], g_wt[1], bk, 1.f, 2, g_k);     // round+perm
    else
        gemm_cp_body(g_x[2], g_wt[2], bv, 1.f, 4, g_vt);    // round+transposed
}

__global__ void __launch_bounds__(256, 2)
out_mma(const float* __restrict__ bo, float* __restrict__ out)
{
    gemm_cp_body(g_o, g_wt[3], bo, 1.f, 0, out);            // plain
}

// ---------------------------------------------------------------------------
// Flash attention, register-resident S/P, transposed V.
// 128 threads, 64-query blocks, 32-key tiles, double-buffered K/VT.
// K rows key-permuted (S C-frag == P A-frag); VT key-permuted columns
// so P@V B-fragments are single LDS.64.
// ---------------------------------------------------------------------------
constexpr int AS = 72;                   // K tile stride  (32 rows x 64 d)
constexpr int VS = 40;                   // VT tile stride (64 rows x 32 keys)
constexpr int K_STAGE = 32 * AS;         // 2304 floats
constexpr int V_STAGE = 64 * VS;         // 2560 floats
constexpr int ATTN_SMEM = 2 * (K_STAGE + V_STAGE) * 4;   // 38912 bytes

__global__ void __launch_bounds__(128) attn_mma()
{
    extern __shared__ float sm[];
    float* Kb[2] = { sm,                          sm + K_STAGE + V_STAGE };
    float* Vb[2] = { sm + K_STAGE,                sm + 2 * K_STAGE + V_STAGE };

    const int t   = threadIdx.x;
    const int wid = t >> 5;
    const int lid = t & 31;
    const int g   = lid >> 2;
    const int tig = lid & 3;
    const int q0  = blockIdx.x * 64;
    const int bh  = blockIdx.y;                 // b*8 + h
    const int b   = bh >> 3;
    const int h   = bh & 7;
    const size_t base  = (size_t)b * SEQ * ND + (size_t)h * DH;
    const float* vtb = g_vt + (size_t)bh * DH * SEQ;   // [dh][perm(seq)]

    const int qrow = wid * 16 + g;

    // Q fragments straight from gmem (pre-scaled/rounded/d-permuted)
    uint32_t qf[8][4];
    {
        const float* qp0 = g_q + base + (size_t)(q0 + qrow) * ND;
        const float* qp1 = qp0 + 8 * ND;
        #pragma unroll
        for (int ks = 0; ks < 8; ks++) {
            float2 p0 = *(const float2*)(qp0 + ks * 8 + 2 * tig);
            float2 p1 = *(const float2*)(qp1 + ks * 8 + 2 * tig);
            qf[ks][0] = __float_as_uint(p0.x);
            qf[ks][1] = __float_as_uint(p1.x);
            qf[ks][2] = __float_as_uint(p0.y);
            qf[ks][3] = __float_as_uint(p1.y);
        }
    }

    auto load_kv = [&](int s, int k0) {
        // K: 32 key rows x 64 d, rows key-permuted
        #pragma unroll
        for (int i = 0; i < 4; i++) {
            int idx = t + i * 128;      // 0..511
            int r   = idx >> 4;         // key row 0..31
            int c4  = (idx & 15) << 2;
            int rp  = (r & ~7) | f8(r & 7);
            cp16(smem_u32(&Kb[s][rp * AS + c4]),
                 g_k + base + (size_t)(k0 + r) * ND + c4);
        }
        // VT: 64 d rows x 32 keys (keys pre-permuted in gmem)
        #pragma unroll
        for (int i = 0; i < 4; i++) {
            int idx = t + i * 128;      // 0..511
            int r   = idx >> 3;         // d row 0..63
            int c4  = (idx & 7) << 2;   // key offset 0,4,...,28
            cp16(smem_u32(&Vb[s][r * VS + c4]),
                 vtb + (size_t)r * SEQ + k0 + c4);
        }
        CP_COMMIT();
    };
    load_kv(0, 0);

    float m0 = -1e30f, m1 = -1e30f, l0 = 0.f, l1 = 0.f;
    float oacc[8][4] = {};

    for (int kt = 0; kt < 32; kt++) {
        if (kt < 31) { load_kv((kt + 1) & 1, (kt + 1) * 32); CP_WAIT(1); }
        else         { CP_WAIT(0); }
        __syncthreads();

        const float* Ks = Kb[kt & 1];
        const float* Vs = Vb[kt & 1];

        // S = Q @ K^T (log2-domain scores)
        float sfr[4][4] = {};
        #pragma unroll
        for (int ks = 0; ks < 8; ks++) {
            const int kk = ks * 8;
            #pragma unroll
            for (int nt = 0; nt < 4; nt++) {
                uint32_t bfr[2];
                float2 pb = *(const float2*)&Ks[(nt * 8 + g) * AS + kk + 2 * tig];
                bfr[0] = __float_as_uint(pb.x);
                bfr[1] = __float_as_uint(pb.y);
                mma_tf32(sfr[nt], qf[ks], bfr);
            }
        }

        // Register softmax (exp2 domain), quad reduce
        float mx0 = -1e30f, mx1 = -1e30f;
        #pragma unroll
        for (int nt = 0; nt < 4; nt++) {
            mx0 = fmaxf(mx0, fmaxf(sfr[nt][0], sfr[nt][1]));
            mx1 = fmaxf(mx1, fmaxf(sfr[nt][2], sfr[nt][3]));
        }
        mx0 = fmaxf(mx0, __shfl_xor_sync(0xFFFFFFFF, mx0, 1));
        mx0 = fmaxf(mx0, __shfl_xor_sync(0xFFFFFFFF, mx0, 2));
        mx1 = fmaxf(mx1, __shfl_xor_sync(0xFFFFFFFF, mx1, 1));
        mx1 = fmaxf(mx1, __shfl_xor_sync(0xFFFFFFFF, mx1, 2));

        float nm0 = fmaxf(m0, mx0);
        float nm1 = fmaxf(m1, mx1);
        float f0  = exp2f(m0 - nm0);
        float f1  = exp2f(m1 - nm1);
        float sum0 = 0.f, sum1 = 0.f;
        #pragma unroll
        for (int nt = 0; nt < 4; nt++) {
            sfr[nt][0] = exp2f(sfr[nt][0] - nm0);
            sfr[nt][1] = exp2f(sfr[nt][1] - nm0);
            sfr[nt][2] = exp2f(sfr[nt][2] - nm1);
            sfr[nt][3] = exp2f(sfr[nt][3] - nm1);
            sum0 += sfr[nt][0] + sfr[nt][1];
            sum1 += sfr[nt][2] + sfr[nt][3];
        }
        sum0 += __shfl_xor_sync(0xFFFFFFFF, sum0, 1);
        sum0 += __shfl_xor_sync(0xFFFFFFFF, sum0, 2);
        sum1 += __shfl_xor_sync(0xFFFFFFFF, sum1, 1);
        sum1 += __shfl_xor_sync(0xFFFFFFFF, sum1, 2);
        l0 = l0 * f0 + sum0;  m0 = nm0;
        l1 = l1 * f1 + sum1;  m1 = nm1;

        // Rescale running O
        #pragma unroll
        for (int nt = 0; nt < 8; nt++) {
            oacc[nt][0] *= f0;  oacc[nt][1] *= f0;
            oacc[nt][2] *= f1;  oacc[nt][3] *= f1;
        }

        // P @ V : A-frags from sfr, B-frags single LDS.64 from VT
        #pragma unroll
        for (int ks = 0; ks < 4; ks++) {
            uint32_t afr[4];
            afr[0] = f2tf32(sfr[ks][0]);   // P[g][8ks+tig]
            afr[1] = f2tf32(sfr[ks][2]);   // P[g+8][8ks+tig]
            afr[2] = f2tf32(sfr[ks][1]);   // P[g][8ks+tig+4]
            afr[3] = f2tf32(sfr[ks][3]);   // P[g+8][8ks+tig+4]
            const int kk = ks * 8;
            #pragma unroll
            for (int nt = 0; nt < 8; nt++) {
                uint32_t bfr[2];
                float2 pv = *(const float2*)&Vs[(nt * 8 + g) * VS + kk + 2 * tig];
                bfr[0] = __float_as_uint(pv.x);
                bfr[1] = __float_as_uint(pv.y);
                mma_tf32(oacc[nt], afr, bfr);
            }
        }
        __syncthreads();
    }

    // Normalize, round, d-permute, write O
    const int pe = f8(2 * tig);
    const int po = f8(2 * tig + 1);
    float inv0 = 1.f / l0;
    float inv1 = 1.f / l1;
    #pragma unroll
    for (int nt = 0; nt < 8; nt++) {
        float* r0 = g_o + base + (size_t)(q0 + qrow) * ND + nt * 8;
        float* r1 = g_o + base + (size_t)(q0 + qrow + 8) * ND + nt * 8;
        r0[pe] = rtf(oacc[nt][0] * inv0);
        r0[po] = rtf(oacc[nt][1] * inv0);
        r1[pe] = rtf(oacc[nt][2] * inv1);
        r1[po] = rtf(oacc[nt][3] * inv1);
    }
}

// ---------------------------------------------------------------------------
extern "C" void kernel_launch(void* const* d_in, const int* in_sizes, int n_in,
                              void* d_out, int out_size)
{
    const float* q  = (const float*)d_in[0];
    const float* k  = (const float*)d_in[1];
    const float* v  = (const float*)d_in[2];
    const float* Wq = (const float*)d_in[3];
    const float* bq = (const float*)d_in[4];
    const float* Wk = (const float*)d_in[5];
    const float* bk = (const float*)d_in[6];
    const float* Wv = (const float*)d_in[7];
    const float* bv = (const float*)d_in[8];
    const float* Wo = (const float*)d_in[9];
    const float* bo = (const float*)d_in[10];

    static bool attr_done = false;
    if (!attr_done) {
        cudaFuncSetAttribute(qkv_mma, cudaFuncAttributeMaxDynamicSharedMemorySize, GEMM_SMEM);
        cudaFuncSetAttribute(out_mma, cudaFuncAttributeMaxDynamicSharedMemorySize, GEMM_SMEM);
        cudaFuncSetAttribute(attn_mma, cudaFuncAttributeMaxDynamicSharedMemorySize, ATTN_SMEM);
        attr_done = true;
    }

    round_inputs<<<dim3(512, 3), 256>>>(q, k, v);
    transposeW<<<dim3(16, 16, 4), dim3(32, 8)>>>(Wq, Wk, Wv, Wo);
    qkv_mma<<<dim3(ND / 128, Mrows / 128, 3), 256, GEMM_SMEM>>>(bq, bk, bv);
    attn_mma<<<dim3(SEQ / 64, Bb * Hh), 128, ATTN_SMEM>>>();
    out_mma<<<dim3(ND / 128, Mrows / 128), 256, GEMM_SMEM>>>(bo, (float*)d_out);
}